// round 3
// baseline (speedup 1.0000x reference)
#include <cuda_runtime.h>
#include <cuda_bf16.h>
#include <math.h>

#define EMBED 1024
#define NHEAD 16
#define DK    64
#define BATCH 4
#define SEQ   2048
#define MTOK  (BATCH*SEQ)   // 8192

// -------- scratch (device globals; no allocation allowed) --------
__device__ float g_q[(size_t)BATCH*NHEAD*SEQ*DK];   // [b,h,s,d], pre-scaled by 1/sqrt(DK)
__device__ float g_k[(size_t)BATCH*NHEAD*SEQ*DK];
__device__ float g_v[(size_t)BATCH*NHEAD*SEQ*DK];
__device__ float g_attn[(size_t)MTOK*EMBED];        // [b,s,e] attention output

// -------- helpers --------
__device__ __forceinline__ unsigned f2tf(float f) {
    unsigned u; asm("cvt.rna.tf32.f32 %0, %1;" : "=r"(u) : "f"(f)); return u;
}
__device__ __forceinline__ uint4 f2tf4(float4 v) {
    return make_uint4(f2tf(v.x), f2tf(v.y), f2tf(v.z), f2tf(v.w));
}

__device__ __forceinline__ void mma8(float* c, const unsigned* a, const unsigned* b) {
    asm volatile("mma.sync.aligned.m16n8k8.row.col.f32.tf32.tf32.f32 "
        "{%0,%1,%2,%3},{%4,%5,%6,%7},{%8,%9},{%0,%1,%2,%3};"
        : "+f"(c[0]), "+f"(c[1]), "+f"(c[2]), "+f"(c[3])
        : "r"(a[0]), "r"(a[1]), "r"(a[2]), "r"(a[3]), "r"(b[0]), "r"(b[1]));
}

// ldmatrix x4: 4 8-row x 16-byte submatrices. For 32-bit data: thread t reg r =
// tf32 element (t&3) of the 16B row addressed by lane 8r + (t>>2).
__device__ __forceinline__ void ldsm4(unsigned& r0, unsigned& r1, unsigned& r2, unsigned& r3,
                                      const unsigned* p) {
    unsigned a = (unsigned)__cvta_generic_to_shared(p);
    asm volatile("ldmatrix.sync.aligned.m8n8.x4.shared.b16 {%0,%1,%2,%3},[%4];"
        : "=r"(r0), "=r"(r1), "=r"(r2), "=r"(r3) : "r"(a));
}

// swizzles (4-float granularity) to limit LDS bank conflicts
__device__ __forceinline__ int sw16(int m, int k) {
    return m*16 + (((((k) >> 2) ^ (m & 3)) << 2) | (k & 3));
}
__device__ __forceinline__ int sw64(int r, int c) {
    return r*64 + (((((c) >> 2) ^ (r & 7)) << 2) | (c & 3));
}

#define GBUF (128*16)

// ============ 128x128 NT GEMM core (C = A[M,K] * W[N,K]^T), K=1024 ============
// 256 threads = 8 warps in 4(m) x 2(n); warp tile 32x64 = 2 mtiles x 8 ntiles.
// Double-buffered smem (one barrier/ktile), ldmatrix fragment loads.
__device__ __forceinline__ void gemm_core(
    const float* __restrict__ A, const float* __restrict__ W,
    int row0, int col0, unsigned* As, unsigned* Bs, float acc[2][8][4])
{
    const int K = EMBED;
    int tid  = threadIdx.x;
    int lane = tid & 31, wid = tid >> 5;
    int wm = wid >> 1, wn = wid & 1;

    #pragma unroll
    for (int mt = 0; mt < 2; mt++)
        #pragma unroll
        for (int nt = 0; nt < 8; nt++)
            #pragma unroll
            for (int i = 0; i < 4; i++) acc[mt][nt][i] = 0.f;

    int fr[2], fc[2];
    #pragma unroll
    for (int i = 0; i < 2; i++) { int f = tid + 256*i; fr[i] = f >> 2; fc[i] = (f & 3) * 4; }

    // precomputed ldmatrix source offsets (element index within one 128x16 buffer)
    int offA[2][2], offB[4][2];
    {
        int eA = (lane & 16) ? 4 : 0;
        int eB = (lane & 8)  ? 4 : 0;
        #pragma unroll
        for (int mt = 0; mt < 2; mt++) {
            int r = wm*32 + mt*16 + (lane & 15);
            #pragma unroll
            for (int k2 = 0; k2 < 2; k2++) offA[mt][k2] = sw16(r, k2*8 + eA);
        }
        #pragma unroll
        for (int p = 0; p < 4; p++) {
            int r = wn*64 + p*16 + (lane & 7) + ((lane >> 4) & 1) * 8;
            #pragma unroll
            for (int k2 = 0; k2 < 2; k2++) offB[p][k2] = sw16(r, k2*8 + eB);
        }
    }

    float4 pa[2], pb[2];
    auto LDG = [&](int kb) {
        #pragma unroll
        for (int i = 0; i < 2; i++) {
            pa[i] = *(const float4*)(A + (size_t)(row0 + fr[i]) * K + kb + fc[i]);
            pb[i] = *(const float4*)(W + (size_t)(col0 + fr[i]) * K + kb + fc[i]);
        }
    };
    auto STS = [&](unsigned* Ab, unsigned* Bb) {
        #pragma unroll
        for (int i = 0; i < 2; i++) {
            int ad = sw16(fr[i], fc[i]);
            *(uint4*)(Ab + ad) = f2tf4(pa[i]);
            *(uint4*)(Bb + ad) = f2tf4(pb[i]);
        }
    };

    LDG(0); STS(As, Bs); __syncthreads();
    const int NK = K / 16;
    for (int kt = 0; kt < NK; kt++) {
        const unsigned* Ab = As + (kt & 1) * GBUF;
        const unsigned* Bb = Bs + (kt & 1) * GBUF;
        if (kt + 1 < NK) LDG((kt + 1) * 16);
        #pragma unroll
        for (int k2 = 0; k2 < 2; k2++) {
            unsigned a[2][4], b[8][2];
            #pragma unroll
            for (int mt = 0; mt < 2; mt++)
                ldsm4(a[mt][0], a[mt][1], a[mt][2], a[mt][3], Ab + offA[mt][k2]);
            #pragma unroll
            for (int p = 0; p < 4; p++)
                ldsm4(b[2*p][0], b[2*p][1], b[2*p+1][0], b[2*p+1][1], Bb + offB[p][k2]);
            #pragma unroll
            for (int mt = 0; mt < 2; mt++)
                #pragma unroll
                for (int nt = 0; nt < 8; nt++)
                    mma8(acc[mt][nt], a[mt], b[nt]);
        }
        if (kt + 1 < NK) {
            STS(As + ((kt + 1) & 1) * GBUF, Bs + ((kt + 1) & 1) * GBUF);
            __syncthreads();
        }
    }
}

// ============ Kernel 1: fused QKV projections (grid.z picks Q/K/V) ============
__global__ __launch_bounds__(256) void qkv_kernel(
    const float* __restrict__ x,
    const float* __restrict__ Wq, const float* __restrict__ Wk, const float* __restrict__ Wv)
{
    __shared__ __align__(16) unsigned As[2*GBUF], Bs[2*GBUF];
    int row0 = blockIdx.y * 128, col0 = blockIdx.x * 128;
    const float* W = (blockIdx.z == 0) ? Wq : (blockIdx.z == 1 ? Wk : Wv);
    float* dst     = (blockIdx.z == 0) ? g_q : (blockIdx.z == 1 ? g_k : g_v);
    float scale    = (blockIdx.z == 0) ? 0.125f : 1.0f;   // 1/sqrt(64) folded into Q

    float acc[2][8][4];
    gemm_core(x, W, row0, col0, As, Bs, acc);

    int lane = threadIdx.x & 31, wid = threadIdx.x >> 5;
    int g = lane >> 2, tg = lane & 3, wm = wid >> 1, wn = wid & 1;
    #pragma unroll
    for (int mt = 0; mt < 2; mt++) {
        int r = row0 + wm*32 + mt*16 + g;      // token index
        int bb = r >> 11, ss = r & 2047;
        #pragma unroll
        for (int nt = 0; nt < 8; nt++) {
            int c = col0 + wn*64 + nt*8 + 2*tg;  // feature index
            int h = c >> 6, d = c & 63;
            float* p0 = dst + (((size_t)(bb*NHEAD + h) * SEQ + ss) * DK + d);
            float* p1 = dst + (((size_t)(bb*NHEAD + h) * SEQ + ss + 8) * DK + d);
            p0[0] = acc[mt][nt][0] * scale; p0[1] = acc[mt][nt][1] * scale;
            p1[0] = acc[mt][nt][2] * scale; p1[1] = acc[mt][nt][3] * scale;
        }
    }
}

// ============ Kernel 2: flash attention (64q x 64k tiles, online softmax) ============
// grid (SEQ/64, BATCH*NHEAD), 128 threads = 4 warps, each warp owns 16 q-rows.
// K/V tiles register-prefetched across the k-loop; ldmatrix for QK^T and P side of PV.
__global__ __launch_bounds__(128) void attn_kernel()
{
    __shared__ __align__(16) unsigned Qs[64*64];
    __shared__ __align__(16) unsigned KPs[64*64];   // K tile, later reused for P tile
    __shared__ __align__(16) unsigned Vs[64*64];

    int qt = blockIdx.x, bh = blockIdx.y;
    const float* Qp = g_q + (size_t)bh * SEQ * DK + (size_t)qt * 64 * DK;
    const float* Kp = g_k + (size_t)bh * SEQ * DK;
    const float* Vp = g_v + (size_t)bh * SEQ * DK;

    int tid = threadIdx.x, lane = tid & 31, wid = tid >> 5;
    int g = lane >> 2, tg = lane & 3;
    int r0 = wid*16 + g;     // this thread's first q-row within tile (second is r0+8)

    // ldmatrix offsets (A site reused for Q and P; B sites for K)
    int eA = (lane & 16) ? 4 : 0;
    int rA = wid*16 + (lane & 15);
    int eB = (lane & 8)  ? 4 : 0;
    int rB[4];
    #pragma unroll
    for (int p = 0; p < 4; p++) rB[p] = p*16 + (lane & 7) + ((lane >> 4) & 1) * 8;

    // fill addresses for K/V tiles
    int adS[8], goff[8];
    #pragma unroll
    for (int i = 0; i < 8; i++) {
        int f = tid + 128*i;           // float4 index 0..1023
        int r = f >> 4, c4 = f & 15;
        adS[i]  = r*64 + ((c4 ^ (r & 7)) << 2);
        goff[i] = r*64 + c4*4;
    }

    // load Q tile (convert to tf32, swizzled)
    #pragma unroll
    for (int i = 0; i < 8; i++) {
        float4 v = *(const float4*)(Qp + goff[i]);
        *(uint4*)(Qs + adS[i]) = f2tf4(v);
    }

    // prefetch first K/V tiles into registers
    float4 kreg[8], vreg[8];
    #pragma unroll
    for (int i = 0; i < 8; i++) {
        kreg[i] = *(const float4*)(Kp + goff[i]);
        vreg[i] = *(const float4*)(Vp + goff[i]);
    }

    float o[8][4];
    #pragma unroll
    for (int nt = 0; nt < 8; nt++)
        #pragma unroll
        for (int i = 0; i < 4; i++) o[nt][i] = 0.f;
    float m0 = -1e30f, m1 = -1e30f, l0 = 0.f, l1 = 0.f;

    for (int kt = 0; kt < SEQ/64; kt++) {
        // commit prefetched K/V tiles to smem
        #pragma unroll
        for (int i = 0; i < 8; i++) {
            *(uint4*)(KPs + adS[i]) = f2tf4(kreg[i]);
            *(uint4*)(Vs  + adS[i]) = f2tf4(vreg[i]);
        }
        __syncthreads();

        // issue next tile's loads (latency hidden behind compute below)
        if (kt + 1 < SEQ/64) {
            size_t t = (size_t)(kt + 1) * 64 * DK;
            #pragma unroll
            for (int i = 0; i < 8; i++) {
                kreg[i] = *(const float4*)(Kp + t + goff[i]);
                vreg[i] = *(const float4*)(Vp + t + goff[i]);
            }
        }

        // S = Q * K^T  (warp computes 16x64 stripe)
        float s[8][4];
        #pragma unroll
        for (int nt = 0; nt < 8; nt++)
            #pragma unroll
            for (int i = 0; i < 4; i++) s[nt][i] = 0.f;
        #pragma unroll
        for (int kk = 0; kk < 64; kk += 8) {
            unsigned a[4], b[8][2];
            ldsm4(a[0], a[1], a[2], a[3], Qs + sw64(rA, kk + eA));
            #pragma unroll
            for (int p = 0; p < 4; p++)
                ldsm4(b[2*p][0], b[2*p][1], b[2*p+1][0], b[2*p+1][1],
                      KPs + sw64(rB[p], kk + eB));
            #pragma unroll
            for (int nt = 0; nt < 8; nt++) mma8(s[nt], a, b[nt]);
        }

        // online softmax (rows r0, r0+8); quad (tg) shuffle reductions
        float ml0 = -1e30f, ml1 = -1e30f;
        #pragma unroll
        for (int nt = 0; nt < 8; nt++) {
            ml0 = fmaxf(ml0, fmaxf(s[nt][0], s[nt][1]));
            ml1 = fmaxf(ml1, fmaxf(s[nt][2], s[nt][3]));
        }
        ml0 = fmaxf(ml0, __shfl_xor_sync(0xffffffffu, ml0, 1));
        ml0 = fmaxf(ml0, __shfl_xor_sync(0xffffffffu, ml0, 2));
        ml1 = fmaxf(ml1, __shfl_xor_sync(0xffffffffu, ml1, 1));
        ml1 = fmaxf(ml1, __shfl_xor_sync(0xffffffffu, ml1, 2));
        float mn0 = fmaxf(m0, ml0), mn1 = fmaxf(m1, ml1);
        float al0 = __expf(m0 - mn0), al1 = __expf(m1 - mn1);
        m0 = mn0; m1 = mn1;
        float sum0 = 0.f, sum1 = 0.f;
        #pragma unroll
        for (int nt = 0; nt < 8; nt++) {
            s[nt][0] = __expf(s[nt][0] - mn0); sum0 += s[nt][0];
            s[nt][1] = __expf(s[nt][1] - mn0); sum0 += s[nt][1];
            s[nt][2] = __expf(s[nt][2] - mn1); sum1 += s[nt][2];
            s[nt][3] = __expf(s[nt][3] - mn1); sum1 += s[nt][3];
        }
        sum0 += __shfl_xor_sync(0xffffffffu, sum0, 1);
        sum0 += __shfl_xor_sync(0xffffffffu, sum0, 2);
        sum1 += __shfl_xor_sync(0xffffffffu, sum1, 1);
        sum1 += __shfl_xor_sync(0xffffffffu, sum1, 2);
        l0 = l0 * al0 + sum0;
        l1 = l1 * al1 + sum1;
        #pragma unroll
        for (int nt = 0; nt < 8; nt++) {
            o[nt][0] *= al0; o[nt][1] *= al0;
            o[nt][2] *= al1; o[nt][3] *= al1;
        }

        __syncthreads();   // all warps done reading K tile
        // store P into KPs (tf32)
        #pragma unroll
        for (int nt = 0; nt < 8; nt++) {
            int c = nt*8 + 2*tg;
            KPs[sw64(r0,     c)]     = f2tf(s[nt][0]);
            KPs[sw64(r0,     c + 1)] = f2tf(s[nt][1]);
            KPs[sw64(r0 + 8, c)]     = f2tf(s[nt][2]);
            KPs[sw64(r0 + 8, c + 1)] = f2tf(s[nt][3]);
        }
        __syncthreads();

        // O += P * V  (A = P [64q x 64k] via ldmatrix, B = V [64k x 64d] scalar)
        #pragma unroll
        for (int kk = 0; kk < 64; kk += 8) {
            unsigned a[4], b[8][2];
            ldsm4(a[0], a[1], a[2], a[3], KPs + sw64(rA, kk + eA));
            #pragma unroll
            for (int nt = 0; nt < 8; nt++) {
                b[nt][0] = Vs[sw64(kk + tg,     nt*8 + g)];
                b[nt][1] = Vs[sw64(kk + tg + 4, nt*8 + g)];
            }
            #pragma unroll
            for (int nt = 0; nt < 8; nt++) mma8(o[nt], a, b[nt]);
        }
        __syncthreads();   // protect KPs/Vs before next tile's fill
    }

    // epilogue: normalize and write to g_attn[b, s, h*64+d]
    float inv0 = 1.f / l0, inv1 = 1.f / l1;
    int bb = bh >> 4, h = bh & 15;
    int q0 = qt*64 + r0;
    float* base0 = g_attn + ((size_t)(bb*SEQ + q0) * EMBED) + h*64;
    float* base1 = base0 + (size_t)8 * EMBED;
    #pragma unroll
    for (int nt = 0; nt < 8; nt++) {
        int d = nt*8 + 2*tg;
        base0[d]     = o[nt][0] * inv0;
        base0[d + 1] = o[nt][1] * inv0;
        base1[d]     = o[nt][2] * inv1;
        base1[d + 1] = o[nt][3] * inv1;
    }
}

// ============ Kernel 3: output projection ============
__global__ __launch_bounds__(256) void oproj_kernel(const float* __restrict__ Wo, float* __restrict__ out)
{
    __shared__ __align__(16) unsigned As[2*GBUF], Bs[2*GBUF];
    int row0 = blockIdx.y * 128, col0 = blockIdx.x * 128;
    float acc[2][8][4];
    gemm_core(g_attn, Wo, row0, col0, As, Bs, acc);

    int lane = threadIdx.x & 31, wid = threadIdx.x >> 5;
    int g = lane >> 2, tg = lane & 3, wm = wid >> 1, wn = wid & 1;
    #pragma unroll
    for (int mt = 0; mt < 2; mt++) {
        int r = row0 + wm*32 + mt*16 + g;
        #pragma unroll
        for (int nt = 0; nt < 8; nt++) {
            int c = col0 + wn*64 + nt*8 + 2*tg;
            float* p0 = out + (size_t)r * EMBED + c;
            float* p1 = out + (size_t)(r + 8) * EMBED + c;
            p0[0] = acc[mt][nt][0]; p0[1] = acc[mt][nt][1];
            p1[0] = acc[mt][nt][2]; p1[1] = acc[mt][nt][3];
        }
    }
}

// ============ launch ============
extern "C" void kernel_launch(void* const* d_in, const int* in_sizes, int n_in,
                              void* d_out, int out_size)
{
    const float* x  = (const float*)d_in[0];
    const float* Wq = (const float*)d_in[1];
    const float* Wk = (const float*)d_in[2];
    const float* Wv = (const float*)d_in[3];
    const float* Wo = (const float*)d_in[4];
    float* out = (float*)d_out;

    qkv_kernel<<<dim3(EMBED/128, MTOK/128, 3), 256>>>(x, Wq, Wk, Wv);
    attn_kernel<<<dim3(SEQ/64, BATCH*NHEAD), 128>>>();
    oproj_kernel<<<dim3(EMBED/128, MTOK/128), 256>>>(Wo, out);
}

// round 4
// speedup vs baseline: 1.6706x; 1.6706x over previous
#include <cuda_runtime.h>
#include <cuda_bf16.h>
#include <math.h>

#define EMBED 1024
#define NHEAD 16
#define DK    64
#define BATCH 4
#define SEQ   2048
#define MTOK  (BATCH*SEQ)   // 8192

// -------- scratch (device globals; no allocation allowed) --------
__device__ float g_q[(size_t)BATCH*NHEAD*SEQ*DK];   // [b,h,s,d], pre-scaled by 1/sqrt(DK)
__device__ float g_k[(size_t)BATCH*NHEAD*SEQ*DK];
__device__ float g_v[(size_t)BATCH*NHEAD*SEQ*DK];
__device__ float g_attn[(size_t)MTOK*EMBED];        // [b,s,e] attention output

// -------- helpers --------
__device__ __forceinline__ unsigned f2tf(float f) {
    unsigned u; asm("cvt.rna.tf32.f32 %0, %1;" : "=r"(u) : "f"(f)); return u;
}
__device__ __forceinline__ uint4 f2tf4(float4 v) {
    return make_uint4(f2tf(v.x), f2tf(v.y), f2tf(v.z), f2tf(v.w));
}

__device__ __forceinline__ void mma8(float* c, const unsigned* a, const unsigned* b) {
    asm volatile("mma.sync.aligned.m16n8k8.row.col.f32.tf32.tf32.f32 "
        "{%0,%1,%2,%3},{%4,%5,%6,%7},{%8,%9},{%0,%1,%2,%3};"
        : "+f"(c[0]), "+f"(c[1]), "+f"(c[2]), "+f"(c[3])
        : "r"(a[0]), "r"(a[1]), "r"(a[2]), "r"(a[3]), "r"(b[0]), "r"(b[1]));
}

// ldmatrix x4: for 32-bit data, thread t reg r = element (t&3) of the 16B row
// addressed by lane 8r+(t>>2).
__device__ __forceinline__ void ldsm4(unsigned& r0, unsigned& r1, unsigned& r2, unsigned& r3,
                                      const unsigned* p) {
    unsigned a = (unsigned)__cvta_generic_to_shared(p);
    asm volatile("ldmatrix.sync.aligned.m8n8.x4.shared.b16 {%0,%1,%2,%3},[%4];"
        : "=r"(r0), "=r"(r1), "=r"(r2), "=r"(r3) : "r"(a));
}

// 128B-row swizzles: full 8-group XOR -> conflict-free STS.128 and LDSM
__device__ __forceinline__ int sw32(int m, int k) {   // rows of 32 floats
    return m*32 + (((((k) >> 2) ^ (m & 7)) << 2) | (k & 3));
}
__device__ __forceinline__ int sw64(int r, int c) {   // rows of 64 floats
    return r*64 + (((((c) >> 2) ^ (r & 7)) << 2) | (c & 3));
}

#define BK   32
#define GBUF (128*BK)   // elements per tile buffer

// ============ 128x128 NT GEMM core (C = A[M,K] * W[N,K]^T), K=1024 ============
// 256 threads = 8 warps in 4(m) x 2(n); warp tile 32x64 = 2 mtiles x 8 ntiles.
// BK=32 (128B rows), double-buffered smem, ldmatrix fragment loads.
__device__ __forceinline__ void gemm_core(
    const float* __restrict__ A, const float* __restrict__ W,
    int row0, int col0, unsigned* As, unsigned* Bs, float acc[2][8][4])
{
    const int K = EMBED;
    int tid  = threadIdx.x;
    int lane = tid & 31, wid = tid >> 5;
    int wm = wid >> 1, wn = wid & 1;

    #pragma unroll
    for (int mt = 0; mt < 2; mt++)
        #pragma unroll
        for (int nt = 0; nt < 8; nt++)
            #pragma unroll
            for (int i = 0; i < 4; i++) acc[mt][nt][i] = 0.f;

    int fr[4], fc[4];
    #pragma unroll
    for (int i = 0; i < 4; i++) { int f = tid + 256*i; fr[i] = f >> 3; fc[i] = (f & 7) * 4; }

    // precomputed ldmatrix source offsets (4 k-slices per BK=32 tile)
    int offA[2][4], offB[4][4];
    {
        int eA = (lane & 16) ? 4 : 0;
        int eB = (lane & 8)  ? 4 : 0;
        #pragma unroll
        for (int mt = 0; mt < 2; mt++) {
            int r = wm*32 + mt*16 + (lane & 15);
            #pragma unroll
            for (int s = 0; s < 4; s++) offA[mt][s] = sw32(r, s*8 + eA);
        }
        #pragma unroll
        for (int p = 0; p < 4; p++) {
            int r = wn*64 + p*16 + (lane & 7) + ((lane >> 4) & 1) * 8;
            #pragma unroll
            for (int s = 0; s < 4; s++) offB[p][s] = sw32(r, s*8 + eB);
        }
    }

    float4 pa[4], pb[4];
    auto LDG = [&](int kb) {
        #pragma unroll
        for (int i = 0; i < 4; i++) {
            pa[i] = *(const float4*)(A + (size_t)(row0 + fr[i]) * K + kb + fc[i]);
            pb[i] = *(const float4*)(W + (size_t)(col0 + fr[i]) * K + kb + fc[i]);
        }
    };
    auto STS = [&](unsigned* Ab, unsigned* Bb) {
        #pragma unroll
        for (int i = 0; i < 4; i++) {
            int ad = sw32(fr[i], fc[i]);
            *(uint4*)(Ab + ad) = f2tf4(pa[i]);
            *(uint4*)(Bb + ad) = f2tf4(pb[i]);
        }
    };

    LDG(0); STS(As, Bs); __syncthreads();
    const int NK = K / BK;   // 32
    for (int kt = 0; kt < NK; kt++) {
        const unsigned* Ab = As + (kt & 1) * GBUF;
        const unsigned* Bb = Bs + (kt & 1) * GBUF;
        if (kt + 1 < NK) LDG((kt + 1) * BK);
        #pragma unroll
        for (int s = 0; s < 4; s++) {
            unsigned a[2][4], b[8][2];
            #pragma unroll
            for (int mt = 0; mt < 2; mt++)
                ldsm4(a[mt][0], a[mt][1], a[mt][2], a[mt][3], Ab + offA[mt][s]);
            #pragma unroll
            for (int p = 0; p < 4; p++)
                ldsm4(b[2*p][0], b[2*p][1], b[2*p+1][0], b[2*p+1][1], Bb + offB[p][s]);
            #pragma unroll
            for (int mt = 0; mt < 2; mt++)
                #pragma unroll
                for (int nt = 0; nt < 8; nt++)
                    mma8(acc[mt][nt], a[mt], b[nt]);
        }
        if (kt + 1 < NK) {
            STS(As + ((kt + 1) & 1) * GBUF, Bs + ((kt + 1) & 1) * GBUF);
            __syncthreads();
        }
    }
}

// dynamic smem: [As buf0][As buf1][Bs buf0][Bs buf1] = 4*GBUF unsigned = 64KB
#define GEMM_SMEM_BYTES (4 * GBUF * (int)sizeof(unsigned))

// ============ Kernel 1: fused QKV projections (grid.z picks Q/K/V) ============
__global__ __launch_bounds__(256) void qkv_kernel(
    const float* __restrict__ x,
    const float* __restrict__ Wq, const float* __restrict__ Wk, const float* __restrict__ Wv)
{
    extern __shared__ __align__(16) unsigned smem[];
    unsigned* As = smem;
    unsigned* Bs = smem + 2*GBUF;
    int row0 = blockIdx.y * 128, col0 = blockIdx.x * 128;
    const float* W = (blockIdx.z == 0) ? Wq : (blockIdx.z == 1 ? Wk : Wv);
    float* dst     = (blockIdx.z == 0) ? g_q : (blockIdx.z == 1 ? g_k : g_v);
    float scale    = (blockIdx.z == 0) ? 0.125f : 1.0f;   // 1/sqrt(64) folded into Q

    float acc[2][8][4];
    gemm_core(x, W, row0, col0, As, Bs, acc);

    int lane = threadIdx.x & 31, wid = threadIdx.x >> 5;
    int g = lane >> 2, tg = lane & 3, wm = wid >> 1, wn = wid & 1;
    #pragma unroll
    for (int mt = 0; mt < 2; mt++) {
        int r = row0 + wm*32 + mt*16 + g;      // token index
        int bb = r >> 11, ss = r & 2047;
        #pragma unroll
        for (int nt = 0; nt < 8; nt++) {
            int c = col0 + wn*64 + nt*8 + 2*tg;  // feature index
            int h = c >> 6, d = c & 63;
            float* p0 = dst + (((size_t)(bb*NHEAD + h) * SEQ + ss) * DK + d);
            float* p1 = dst + (((size_t)(bb*NHEAD + h) * SEQ + ss + 8) * DK + d);
            p0[0] = acc[mt][nt][0] * scale; p0[1] = acc[mt][nt][1] * scale;
            p1[0] = acc[mt][nt][2] * scale; p1[1] = acc[mt][nt][3] * scale;
        }
    }
}

// ============ Kernel 2: flash attention (64q x 64k tiles, online softmax) ============
// grid (SEQ/64, BATCH*NHEAD), 128 threads = 4 warps, each warp owns 16 q-rows.
// Direct K/V tile fill each iteration (no register prefetch); ldmatrix fragments.
__global__ __launch_bounds__(128) void attn_kernel()
{
    __shared__ __align__(16) unsigned Qs[64*64];
    __shared__ __align__(16) unsigned KPs[64*64];   // K tile, later reused for P tile
    __shared__ __align__(16) unsigned Vs[64*64];

    int qt = blockIdx.x, bh = blockIdx.y;
    const float* Qp = g_q + (size_t)bh * SEQ * DK + (size_t)qt * 64 * DK;
    const float* Kp = g_k + (size_t)bh * SEQ * DK;
    const float* Vp = g_v + (size_t)bh * SEQ * DK;

    int tid = threadIdx.x, lane = tid & 31, wid = tid >> 5;
    int g = lane >> 2, tg = lane & 3;
    int r0 = wid*16 + g;     // this thread's first q-row within tile (second is r0+8)

    // ldmatrix site offsets (A site reused for Q and P; B sites for K)
    int eA = (lane & 16) ? 4 : 0;
    int rA = wid*16 + (lane & 15);
    int eB = (lane & 8)  ? 4 : 0;
    int rB[4];
    #pragma unroll
    for (int p = 0; p < 4; p++) rB[p] = p*16 + (lane & 7) + ((lane >> 4) & 1) * 8;

    // fill addresses for tiles
    int adS[8], goff[8];
    #pragma unroll
    for (int i = 0; i < 8; i++) {
        int f = tid + 128*i;           // float4 index 0..1023
        int r = f >> 4, c4 = f & 15;
        adS[i]  = r*64 + ((c4 ^ (r & 7)) << 2);
        goff[i] = r*64 + c4*4;
    }

    // load Q tile (convert to tf32, swizzled)
    #pragma unroll
    for (int i = 0; i < 8; i++) {
        float4 v = *(const float4*)(Qp + goff[i]);
        *(uint4*)(Qs + adS[i]) = f2tf4(v);
    }

    float o[8][4];
    #pragma unroll
    for (int nt = 0; nt < 8; nt++)
        #pragma unroll
        for (int i = 0; i < 4; i++) o[nt][i] = 0.f;
    float m0 = -1e30f, m1 = -1e30f, l0 = 0.f, l1 = 0.f;

    for (int kt = 0; kt < SEQ/64; kt++) {
        // fill K -> KPs, V -> Vs
        size_t t = (size_t)kt * 64 * DK;
        #pragma unroll
        for (int i = 0; i < 8; i++) {
            float4 kv = *(const float4*)(Kp + t + goff[i]);
            *(uint4*)(KPs + adS[i]) = f2tf4(kv);
            float4 vv = *(const float4*)(Vp + t + goff[i]);
            *(uint4*)(Vs + adS[i]) = f2tf4(vv);
        }
        __syncthreads();

        // S = Q * K^T  (warp computes 16x64 stripe)
        float s[8][4];
        #pragma unroll
        for (int nt = 0; nt < 8; nt++)
            #pragma unroll
            for (int i = 0; i < 4; i++) s[nt][i] = 0.f;
        #pragma unroll
        for (int kk = 0; kk < 64; kk += 8) {
            unsigned a[4], b[8][2];
            ldsm4(a[0], a[1], a[2], a[3], Qs + sw64(rA, kk + eA));
            #pragma unroll
            for (int p = 0; p < 4; p++)
                ldsm4(b[2*p][0], b[2*p][1], b[2*p+1][0], b[2*p+1][1],
                      KPs + sw64(rB[p], kk + eB));
            #pragma unroll
            for (int nt = 0; nt < 8; nt++) mma8(s[nt], a, b[nt]);
        }

        // online softmax (rows r0, r0+8); quad (tg) shuffle reductions
        float ml0 = -1e30f, ml1 = -1e30f;
        #pragma unroll
        for (int nt = 0; nt < 8; nt++) {
            ml0 = fmaxf(ml0, fmaxf(s[nt][0], s[nt][1]));
            ml1 = fmaxf(ml1, fmaxf(s[nt][2], s[nt][3]));
        }
        ml0 = fmaxf(ml0, __shfl_xor_sync(0xffffffffu, ml0, 1));
        ml0 = fmaxf(ml0, __shfl_xor_sync(0xffffffffu, ml0, 2));
        ml1 = fmaxf(ml1, __shfl_xor_sync(0xffffffffu, ml1, 1));
        ml1 = fmaxf(ml1, __shfl_xor_sync(0xffffffffu, ml1, 2));
        float mn0 = fmaxf(m0, ml0), mn1 = fmaxf(m1, ml1);
        float al0 = __expf(m0 - mn0), al1 = __expf(m1 - mn1);
        m0 = mn0; m1 = mn1;
        float sum0 = 0.f, sum1 = 0.f;
        #pragma unroll
        for (int nt = 0; nt < 8; nt++) {
            s[nt][0] = __expf(s[nt][0] - mn0); sum0 += s[nt][0];
            s[nt][1] = __expf(s[nt][1] - mn0); sum0 += s[nt][1];
            s[nt][2] = __expf(s[nt][2] - mn1); sum1 += s[nt][2];
            s[nt][3] = __expf(s[nt][3] - mn1); sum1 += s[nt][3];
        }
        sum0 += __shfl_xor_sync(0xffffffffu, sum0, 1);
        sum0 += __shfl_xor_sync(0xffffffffu, sum0, 2);
        sum1 += __shfl_xor_sync(0xffffffffu, sum1, 1);
        sum1 += __shfl_xor_sync(0xffffffffu, sum1, 2);
        l0 = l0 * al0 + sum0;
        l1 = l1 * al1 + sum1;
        #pragma unroll
        for (int nt = 0; nt < 8; nt++) {
            o[nt][0] *= al0; o[nt][1] *= al0;
            o[nt][2] *= al1; o[nt][3] *= al1;
        }

        __syncthreads();   // all warps done reading K tile
        // store P into KPs (tf32)
        #pragma unroll
        for (int nt = 0; nt < 8; nt++) {
            int c = nt*8 + 2*tg;
            KPs[sw64(r0,     c)]     = f2tf(s[nt][0]);
            KPs[sw64(r0,     c + 1)] = f2tf(s[nt][1]);
            KPs[sw64(r0 + 8, c)]     = f2tf(s[nt][2]);
            KPs[sw64(r0 + 8, c + 1)] = f2tf(s[nt][3]);
        }
        __syncthreads();

        // O += P * V  (A = P [64q x 64k] via ldmatrix, B = V [64k x 64d] scalar)
        #pragma unroll
        for (int kk = 0; kk < 64; kk += 8) {
            unsigned a[4], b[8][2];
            ldsm4(a[0], a[1], a[2], a[3], KPs + sw64(rA, kk + eA));
            #pragma unroll
            for (int nt = 0; nt < 8; nt++) {
                b[nt][0] = Vs[sw64(kk + tg,     nt*8 + g)];
                b[nt][1] = Vs[sw64(kk + tg + 4, nt*8 + g)];
            }
            #pragma unroll
            for (int nt = 0; nt < 8; nt++) mma8(o[nt], a, b[nt]);
        }
        __syncthreads();   // protect KPs/Vs before next tile's fill
    }

    // epilogue: normalize and write to g_attn[b, s, h*64+d]
    float inv0 = 1.f / l0, inv1 = 1.f / l1;
    int bb = bh >> 4, h = bh & 15;
    int q0 = qt*64 + r0;
    float* base0 = g_attn + ((size_t)(bb*SEQ + q0) * EMBED) + h*64;
    float* base1 = base0 + (size_t)8 * EMBED;
    #pragma unroll
    for (int nt = 0; nt < 8; nt++) {
        int d = nt*8 + 2*tg;
        base0[d]     = o[nt][0] * inv0;
        base0[d + 1] = o[nt][1] * inv0;
        base1[d]     = o[nt][2] * inv1;
        base1[d + 1] = o[nt][3] * inv1;
    }
}

// ============ Kernel 3: output projection ============
__global__ __launch_bounds__(256) void oproj_kernel(const float* __restrict__ Wo, float* __restrict__ out)
{
    extern __shared__ __align__(16) unsigned smem[];
    unsigned* As = smem;
    unsigned* Bs = smem + 2*GBUF;
    int row0 = blockIdx.y * 128, col0 = blockIdx.x * 128;
    float acc[2][8][4];
    gemm_core(g_attn, Wo, row0, col0, As, Bs, acc);

    int lane = threadIdx.x & 31, wid = threadIdx.x >> 5;
    int g = lane >> 2, tg = lane & 3, wm = wid >> 1, wn = wid & 1;
    #pragma unroll
    for (int mt = 0; mt < 2; mt++) {
        int r = row0 + wm*32 + mt*16 + g;
        #pragma unroll
        for (int nt = 0; nt < 8; nt++) {
            int c = col0 + wn*64 + nt*8 + 2*tg;
            float* p0 = out + (size_t)r * EMBED + c;
            float* p1 = out + (size_t)(r + 8) * EMBED + c;
            p0[0] = acc[mt][nt][0]; p0[1] = acc[mt][nt][1];
            p1[0] = acc[mt][nt][2]; p1[1] = acc[mt][nt][3];
        }
    }
}

// ============ launch ============
extern "C" void kernel_launch(void* const* d_in, const int* in_sizes, int n_in,
                              void* d_out, int out_size)
{
    const float* x  = (const float*)d_in[0];
    const float* Wq = (const float*)d_in[1];
    const float* Wk = (const float*)d_in[2];
    const float* Wv = (const float*)d_in[3];
    const float* Wo = (const float*)d_in[4];
    float* out = (float*)d_out;

    cudaFuncSetAttribute(qkv_kernel,   cudaFuncAttributeMaxDynamicSharedMemorySize, GEMM_SMEM_BYTES);
    cudaFuncSetAttribute(oproj_kernel, cudaFuncAttributeMaxDynamicSharedMemorySize, GEMM_SMEM_BYTES);

    qkv_kernel<<<dim3(EMBED/128, MTOK/128, 3), 256, GEMM_SMEM_BYTES>>>(x, Wq, Wk, Wv);
    attn_kernel<<<dim3(SEQ/64, BATCH*NHEAD), 128>>>();
    oproj_kernel<<<dim3(EMBED/128, MTOK/128), 256, GEMM_SMEM_BYTES>>>(Wo, out);
}

// round 6
// speedup vs baseline: 1.9168x; 1.1474x over previous
#include <cuda_runtime.h>
#include <cuda_bf16.h>
#include <math.h>

#define EMBED 1024
#define NHEAD 16
#define DK    64
#define BATCH 4
#define SEQ   2048
#define MTOK  (BATCH*SEQ)   // 8192

// -------- scratch (device globals; no allocation allowed) --------
__device__ float g_x [(size_t)MTOK*EMBED];          // x in tf32 bits
__device__ float g_wq[(size_t)EMBED*EMBED];         // weights in tf32 bits
__device__ float g_wk[(size_t)EMBED*EMBED];
__device__ float g_wv[(size_t)EMBED*EMBED];
__device__ float g_wo[(size_t)EMBED*EMBED];
__device__ float g_q[(size_t)BATCH*NHEAD*SEQ*DK];   // tf32 bits, pre-scaled by 1/8
__device__ float g_k[(size_t)BATCH*NHEAD*SEQ*DK];
__device__ float g_v[(size_t)BATCH*NHEAD*SEQ*DK];
__device__ float g_attn[(size_t)MTOK*EMBED];        // tf32 bits

// -------- helpers --------
__device__ __forceinline__ unsigned f2tf(float f) {
    unsigned u; asm("cvt.rna.tf32.f32 %0, %1;" : "=r"(u) : "f"(f)); return u;
}
__device__ __forceinline__ float f2tff(float f) {
    return __uint_as_float(f2tf(f));
}

__device__ __forceinline__ void mma8(float* c, const unsigned* a, const unsigned* b) {
    asm volatile("mma.sync.aligned.m16n8k8.row.col.f32.tf32.tf32.f32 "
        "{%0,%1,%2,%3},{%4,%5,%6,%7},{%8,%9},{%0,%1,%2,%3};"
        : "+f"(c[0]), "+f"(c[1]), "+f"(c[2]), "+f"(c[3])
        : "r"(a[0]), "r"(a[1]), "r"(a[2]), "r"(a[3]), "r"(b[0]), "r"(b[1]));
}

__device__ __forceinline__ void ldsm4(unsigned& r0, unsigned& r1, unsigned& r2, unsigned& r3,
                                      const unsigned* p) {
    unsigned a = (unsigned)__cvta_generic_to_shared(p);
    asm volatile("ldmatrix.sync.aligned.m8n8.x4.shared.b16 {%0,%1,%2,%3},[%4];"
        : "=r"(r0), "=r"(r1), "=r"(r2), "=r"(r3) : "r"(a));
}

__device__ __forceinline__ void cpa16(unsigned* dst, const void* src) {
    unsigned d = (unsigned)__cvta_generic_to_shared(dst);
    asm volatile("cp.async.ca.shared.global [%0], [%1], 16;" :: "r"(d), "l"(src));
}
#define CP_COMMIT() asm volatile("cp.async.commit_group;")
#define CP_WAIT(N)  asm volatile("cp.async.wait_group %0;" :: "n"(N))

// 128B-row swizzles: full 8-group XOR -> conflict-free STS/LDGSTS.128 and LDSM
__device__ __forceinline__ int sw32(int m, int k) {   // rows of 32 floats
    return m*32 + (((((k) >> 2) ^ (m & 7)) << 2) | (k & 3));
}
__device__ __forceinline__ int sw64(int r, int c) {   // rows of 64 floats
    return r*64 + (((((c) >> 2) ^ (r & 7)) << 2) | (c & 3));
}

#define BK     32
#define TBUF   (128*BK)       // elems of one A or B tile
#define STG    (2*TBUF)       // elems per pipeline stage (A+B)
#define NSTAGE 3
#define GEMM_SMEM_BYTES (NSTAGE * STG * (int)sizeof(unsigned))   // 96KB

// ============ kernel 0: tf32 pre-conversion ============
__global__ __launch_bounds__(256) void prep_kernel(const float* __restrict__ src,
                                                   float* __restrict__ dst, int n4)
{
    int i = blockIdx.x * blockDim.x + threadIdx.x;
    if (i < n4) {
        float4 v = ((const float4*)src)[i];
        v.x = f2tff(v.x); v.y = f2tff(v.y); v.z = f2tff(v.z); v.w = f2tff(v.w);
        ((float4*)dst)[i] = v;
    }
}

// ============ 128x128 NT GEMM core, cp.async 3-stage pipeline ============
// A, W already tf32 bits. 256 threads = 8 warps (4m x 2n), warp tile 32x64.
__device__ __forceinline__ void gemm_core(
    const float* __restrict__ A, const float* __restrict__ W,
    int row0, int col0, unsigned* smem, float acc[2][8][4])
{
    const int K = EMBED;
    int tid  = threadIdx.x;
    int lane = tid & 31, wid = tid >> 5;
    int wm = wid >> 1, wn = wid & 1;

    #pragma unroll
    for (int mt = 0; mt < 2; mt++)
        #pragma unroll
        for (int nt = 0; nt < 8; nt++)
            #pragma unroll
            for (int i = 0; i < 4; i++) acc[mt][nt][i] = 0.f;

    int fr[4], fc[4];
    #pragma unroll
    for (int i = 0; i < 4; i++) { int f = tid + 256*i; fr[i] = f >> 3; fc[i] = (f & 7) * 4; }

    int offA[2][4], offB[4][4];
    {
        int eA = (lane & 16) ? 4 : 0;
        int eB = (lane & 8)  ? 4 : 0;
        #pragma unroll
        for (int mt = 0; mt < 2; mt++) {
            int r = wm*32 + mt*16 + (lane & 15);
            #pragma unroll
            for (int s = 0; s < 4; s++) offA[mt][s] = sw32(r, s*8 + eA);
        }
        #pragma unroll
        for (int p = 0; p < 4; p++) {
            int r = wn*64 + p*16 + (lane & 7) + ((lane >> 4) & 1) * 8;
            #pragma unroll
            for (int s = 0; s < 4; s++) offB[p][s] = sw32(r, s*8 + eB);
        }
    }

    const float* Abase = A + (size_t)row0 * K;
    const float* Bbase = W + (size_t)col0 * K;

    auto issue = [&](int kt) {
        unsigned* st = smem + (kt % NSTAGE) * STG;
        const float* Ab = Abase + kt * BK;
        const float* Bb = Bbase + kt * BK;
        #pragma unroll
        for (int i = 0; i < 4; i++)
            cpa16(st + sw32(fr[i], fc[i]), Ab + (size_t)fr[i] * K + fc[i]);
        #pragma unroll
        for (int i = 0; i < 4; i++)
            cpa16(st + TBUF + sw32(fr[i], fc[i]), Bb + (size_t)fr[i] * K + fc[i]);
        CP_COMMIT();
    };

    const int NK = K / BK;   // 32
    issue(0); issue(1);
    for (int kt = 0; kt < NK; kt++) {
        if (kt + 1 < NK) { CP_WAIT(1); } else { CP_WAIT(0); }
        __syncthreads();
        if (kt + 2 < NK) issue(kt + 2);
        const unsigned* Ab = smem + (kt % NSTAGE) * STG;
        const unsigned* Bb = Ab + TBUF;
        #pragma unroll
        for (int s = 0; s < 4; s++) {
            unsigned a[2][4], b[8][2];
            #pragma unroll
            for (int mt = 0; mt < 2; mt++)
                ldsm4(a[mt][0], a[mt][1], a[mt][2], a[mt][3], Ab + offA[mt][s]);
            #pragma unroll
            for (int p = 0; p < 4; p++)
                ldsm4(b[2*p][0], b[2*p][1], b[2*p+1][0], b[2*p+1][1], Bb + offB[p][s]);
            #pragma unroll
            for (int mt = 0; mt < 2; mt++)
                #pragma unroll
                for (int nt = 0; nt < 8; nt++)
                    mma8(acc[mt][nt], a[mt], b[nt]);
        }
    }
}

// ============ Kernel 1: fused QKV projections (grid.z picks Q/K/V) ============
__global__ __launch_bounds__(256, 2) void qkv_kernel()
{
    extern __shared__ __align__(16) unsigned smem[];
    int row0 = blockIdx.y * 128, col0 = blockIdx.x * 128;
    const float* W = (blockIdx.z == 0) ? g_wq : (blockIdx.z == 1 ? g_wk : g_wv);
    float* dst     = (blockIdx.z == 0) ? g_q : (blockIdx.z == 1 ? g_k : g_v);
    float scale    = (blockIdx.z == 0) ? 0.125f : 1.0f;

    float acc[2][8][4];
    gemm_core(g_x, W, row0, col0, smem, acc);

    int lane = threadIdx.x & 31, wid = threadIdx.x >> 5;
    int g = lane >> 2, tg = lane & 3, wm = wid >> 1, wn = wid & 1;
    #pragma unroll
    for (int mt = 0; mt < 2; mt++) {
        int r = row0 + wm*32 + mt*16 + g;
        int bb = r >> 11, ss = r & 2047;
        #pragma unroll
        for (int nt = 0; nt < 8; nt++) {
            int c = col0 + wn*64 + nt*8 + 2*tg;
            int h = c >> 6, d = c & 63;
            float* p0 = dst + (((size_t)(bb*NHEAD + h) * SEQ + ss) * DK + d);
            float* p1 = dst + (((size_t)(bb*NHEAD + h) * SEQ + ss + 8) * DK + d);
            p0[0] = f2tff(acc[mt][nt][0] * scale); p0[1] = f2tff(acc[mt][nt][1] * scale);
            p1[0] = f2tff(acc[mt][nt][2] * scale); p1[1] = f2tff(acc[mt][nt][3] * scale);
        }
    }
}

// ============ Kernel 2: flash attention ============
// 64q x 64k tiles, 128 threads = 4 warps (16 q-rows each).
// Inputs already tf32: cp.async fills, double-buffered K/V, private P buffer.
// smem: [Qs 16KB][Ps 16KB][K0 16][V0 16][K1 16][V1 16] = 96KB dynamic.
#define ATTN_SMEM_BYTES (6 * 64 * 64 * (int)sizeof(unsigned))
__global__ __launch_bounds__(128, 2) void attn_kernel()
{
    extern __shared__ __align__(16) unsigned asm_[];
    unsigned* Qs = asm_;
    unsigned* Ps = asm_ + 4096;
    unsigned* KV = asm_ + 8192;   // stage s: K at s*8192, V at s*8192+4096

    int qt = blockIdx.x, bh = blockIdx.y;
    const float* Qp = g_q + (size_t)bh * SEQ * DK + (size_t)qt * 64 * DK;
    const float* Kp = g_k + (size_t)bh * SEQ * DK;
    const float* Vp = g_v + (size_t)bh * SEQ * DK;

    int tid = threadIdx.x, lane = tid & 31, wid = tid >> 5;
    int g = lane >> 2, tg = lane & 3;
    int r0 = wid*16 + g;

    int eA = (lane & 16) ? 4 : 0;
    int rA = wid*16 + (lane & 15);
    int eB = (lane & 8)  ? 4 : 0;
    int rB[4];
    #pragma unroll
    for (int p = 0; p < 4; p++) rB[p] = p*16 + (lane & 7) + ((lane >> 4) & 1) * 8;

    int adS[8], goff[8];
    #pragma unroll
    for (int i = 0; i < 8; i++) {
        int f = tid + 128*i;
        int r = f >> 4, c4 = f & 15;
        adS[i]  = r*64 + ((c4 ^ (r & 7)) << 2);
        goff[i] = r*64 + c4*4;
    }

    // Q fill + first K/V fill
    #pragma unroll
    for (int i = 0; i < 8; i++) cpa16(Qs + adS[i], Qp + goff[i]);
    CP_COMMIT();
    #pragma unroll
    for (int i = 0; i < 8; i++) {
        cpa16(KV + adS[i],        Kp + goff[i]);
        cpa16(KV + 4096 + adS[i], Vp + goff[i]);
    }
    CP_COMMIT();

    float o[8][4];
    #pragma unroll
    for (int nt = 0; nt < 8; nt++)
        #pragma unroll
        for (int i = 0; i < 4; i++) o[nt][i] = 0.f;
    float m0 = -1e30f, m1 = -1e30f, l0 = 0.f, l1 = 0.f;

    const int NT = SEQ/64;
    for (int kt = 0; kt < NT; kt++) {
        CP_WAIT(0);
        __syncthreads();   // stage ready + all warps done with the stage being refilled

        if (kt + 1 < NT) {
            unsigned* st = KV + ((kt + 1) & 1) * 8192;
            size_t t = (size_t)(kt + 1) * 64 * DK;
            #pragma unroll
            for (int i = 0; i < 8; i++) {
                cpa16(st + adS[i],        Kp + t + goff[i]);
                cpa16(st + 4096 + adS[i], Vp + t + goff[i]);
            }
            CP_COMMIT();
        }

        const unsigned* Ks = KV + (kt & 1) * 8192;
        const unsigned* Vs = Ks + 4096;

        // S = Q * K^T
        float s[8][4];
        #pragma unroll
        for (int nt = 0; nt < 8; nt++)
            #pragma unroll
            for (int i = 0; i < 4; i++) s[nt][i] = 0.f;
        #pragma unroll
        for (int kk = 0; kk < 64; kk += 8) {
            unsigned a[4], b[8][2];
            ldsm4(a[0], a[1], a[2], a[3], Qs + sw64(rA, kk + eA));
            #pragma unroll
            for (int p = 0; p < 4; p++)
                ldsm4(b[2*p][0], b[2*p][1], b[2*p+1][0], b[2*p+1][1],
                      Ks + sw64(rB[p], kk + eB));
            #pragma unroll
            for (int nt = 0; nt < 8; nt++) mma8(s[nt], a, b[nt]);
        }

        // online softmax
        float ml0 = -1e30f, ml1 = -1e30f;
        #pragma unroll
        for (int nt = 0; nt < 8; nt++) {
            ml0 = fmaxf(ml0, fmaxf(s[nt][0], s[nt][1]));
            ml1 = fmaxf(ml1, fmaxf(s[nt][2], s[nt][3]));
        }
        ml0 = fmaxf(ml0, __shfl_xor_sync(0xffffffffu, ml0, 1));
        ml0 = fmaxf(ml0, __shfl_xor_sync(0xffffffffu, ml0, 2));
        ml1 = fmaxf(ml1, __shfl_xor_sync(0xffffffffu, ml1, 1));
        ml1 = fmaxf(ml1, __shfl_xor_sync(0xffffffffu, ml1, 2));
        float mn0 = fmaxf(m0, ml0), mn1 = fmaxf(m1, ml1);
        float al0 = __expf(m0 - mn0), al1 = __expf(m1 - mn1);
        m0 = mn0; m1 = mn1;
        float sum0 = 0.f, sum1 = 0.f;
        #pragma unroll
        for (int nt = 0; nt < 8; nt++) {
            s[nt][0] = __expf(s[nt][0] - mn0); sum0 += s[nt][0];
            s[nt][1] = __expf(s[nt][1] - mn0); sum0 += s[nt][1];
            s[nt][2] = __expf(s[nt][2] - mn1); sum1 += s[nt][2];
            s[nt][3] = __expf(s[nt][3] - mn1); sum1 += s[nt][3];
        }
        sum0 += __shfl_xor_sync(0xffffffffu, sum0, 1);
        sum0 += __shfl_xor_sync(0xffffffffu, sum0, 2);
        sum1 += __shfl_xor_sync(0xffffffffu, sum1, 1);
        sum1 += __shfl_xor_sync(0xffffffffu, sum1, 2);
        l0 = l0 * al0 + sum0;
        l1 = l1 * al1 + sum1;
        #pragma unroll
        for (int nt = 0; nt < 8; nt++) {
            o[nt][0] *= al0; o[nt][1] *= al0;
            o[nt][2] *= al1; o[nt][3] *= al1;
        }

        // P stripe -> Ps (warp-private rows; no block barrier needed)
        #pragma unroll
        for (int nt = 0; nt < 8; nt++) {
            int c = nt*8 + 2*tg;
            Ps[sw64(r0,     c)]     = f2tf(s[nt][0]);
            Ps[sw64(r0,     c + 1)] = f2tf(s[nt][1]);
            Ps[sw64(r0 + 8, c)]     = f2tf(s[nt][2]);
            Ps[sw64(r0 + 8, c + 1)] = f2tf(s[nt][3]);
        }
        __syncwarp();

        // O += P * V
        #pragma unroll
        for (int kk = 0; kk < 64; kk += 8) {
            unsigned a[4], b[8][2];
            ldsm4(a[0], a[1], a[2], a[3], Ps + sw64(rA, kk + eA));
            #pragma unroll
            for (int nt = 0; nt < 8; nt++) {
                b[nt][0] = Vs[sw64(kk + tg,     nt*8 + g)];
                b[nt][1] = Vs[sw64(kk + tg + 4, nt*8 + g)];
            }
            #pragma unroll
            for (int nt = 0; nt < 8; nt++) mma8(o[nt], a, b[nt]);
        }
    }

    // epilogue: normalize, convert to tf32 bits, write g_attn[b, s, h*64+d]
    float inv0 = 1.f / l0, inv1 = 1.f / l1;
    int bb = bh >> 4, h = bh & 15;
    int q0 = qt*64 + r0;
    float* base0 = g_attn + ((size_t)(bb*SEQ + q0) * EMBED) + h*64;
    float* base1 = base0 + (size_t)8 * EMBED;
    #pragma unroll
    for (int nt = 0; nt < 8; nt++) {
        int d = nt*8 + 2*tg;
        base0[d]     = f2tff(o[nt][0] * inv0);
        base0[d + 1] = f2tff(o[nt][1] * inv0);
        base1[d]     = f2tff(o[nt][2] * inv1);
        base1[d + 1] = f2tff(o[nt][3] * inv1);
    }
}

// ============ Kernel 3: output projection ============
__global__ __launch_bounds__(256, 2) void oproj_kernel(float* __restrict__ out)
{
    extern __shared__ __align__(16) unsigned smem[];
    int row0 = blockIdx.y * 128, col0 = blockIdx.x * 128;
    float acc[2][8][4];
    gemm_core(g_attn, g_wo, row0, col0, smem, acc);

    int lane = threadIdx.x & 31, wid = threadIdx.x >> 5;
    int g = lane >> 2, tg = lane & 3, wm = wid >> 1, wn = wid & 1;
    #pragma unroll
    for (int mt = 0; mt < 2; mt++) {
        int r = row0 + wm*32 + mt*16 + g;
        #pragma unroll
        for (int nt = 0; nt < 8; nt++) {
            int c = col0 + wn*64 + nt*8 + 2*tg;
            float* p0 = out + (size_t)r * EMBED + c;
            float* p1 = out + (size_t)(r + 8) * EMBED + c;
            p0[0] = acc[mt][nt][0]; p0[1] = acc[mt][nt][1];
            p1[0] = acc[mt][nt][2]; p1[1] = acc[mt][nt][3];
        }
    }
}

// ============ launch ============
extern "C" void kernel_launch(void* const* d_in, const int* in_sizes, int n_in,
                              void* d_out, int out_size)
{
    const float* x  = (const float*)d_in[0];
    const float* Wq = (const float*)d_in[1];
    const float* Wk = (const float*)d_in[2];
    const float* Wv = (const float*)d_in[3];
    const float* Wo = (const float*)d_in[4];
    float* out = (float*)d_out;

    cudaFuncSetAttribute(qkv_kernel,   cudaFuncAttributeMaxDynamicSharedMemorySize, GEMM_SMEM_BYTES);
    cudaFuncSetAttribute(oproj_kernel, cudaFuncAttributeMaxDynamicSharedMemorySize, GEMM_SMEM_BYTES);
    cudaFuncSetAttribute(attn_kernel,  cudaFuncAttributeMaxDynamicSharedMemorySize, ATTN_SMEM_BYTES);

    float* p_x;  cudaGetSymbolAddress((void**)&p_x,  g_x);
    float* p_wq; cudaGetSymbolAddress((void**)&p_wq, g_wq);
    float* p_wk; cudaGetSymbolAddress((void**)&p_wk, g_wk);
    float* p_wv; cudaGetSymbolAddress((void**)&p_wv, g_wv);
    float* p_wo; cudaGetSymbolAddress((void**)&p_wo, g_wo);

    int nx4 = MTOK*EMBED/4, nw4 = EMBED*EMBED/4;
    prep_kernel<<<(nx4 + 255)/256, 256>>>(x,  p_x,  nx4);
    prep_kernel<<<(nw4 + 255)/256, 256>>>(Wq, p_wq, nw4);
    prep_kernel<<<(nw4 + 255)/256, 256>>>(Wk, p_wk, nw4);
    prep_kernel<<<(nw4 + 255)/256, 256>>>(Wv, p_wv, nw4);
    prep_kernel<<<(nw4 + 255)/256, 256>>>(Wo, p_wo, nw4);

    qkv_kernel<<<dim3(EMBED/128, MTOK/128, 3), 256, GEMM_SMEM_BYTES>>>();
    attn_kernel<<<dim3(SEQ/64, BATCH*NHEAD), 128, ATTN_SMEM_BYTES>>>();
    oproj_kernel<<<dim3(EMBED/128, MTOK/128), 256, GEMM_SMEM_BYTES>>>(out);
}

// round 7
// speedup vs baseline: 2.1892x; 1.1421x over previous
#include <cuda_runtime.h>
#include <cuda_bf16.h>
#include <math.h>

#define EMBED 1024
#define NHEAD 16
#define DK    64
#define BATCH 4
#define SEQ   2048
#define MTOK  (BATCH*SEQ)   // 8192

// -------- scratch (device globals; no allocation allowed) --------
__device__ float g_x [(size_t)MTOK*EMBED];          // x in tf32 bits
__device__ float g_wq[(size_t)EMBED*EMBED];         // weights in tf32 bits
__device__ float g_wk[(size_t)EMBED*EMBED];
__device__ float g_wv[(size_t)EMBED*EMBED];
__device__ float g_wo[(size_t)EMBED*EMBED];
__device__ float g_q[(size_t)BATCH*NHEAD*SEQ*DK];   // [b,h,s,d] tf32 bits, pre-scaled 1/8
__device__ float g_k[(size_t)BATCH*NHEAD*SEQ*DK];   // [b,h,s,d]
__device__ float g_v[(size_t)BATCH*NHEAD*DK*SEQ];   // [b,h,d,s]  (TRANSPOSED)
__device__ float g_attn[(size_t)MTOK*EMBED];        // tf32 bits

// -------- helpers --------
__device__ __forceinline__ unsigned f2tf(float f) {
    unsigned u; asm("cvt.rna.tf32.f32 %0, %1;" : "=r"(u) : "f"(f)); return u;
}
__device__ __forceinline__ float f2tff(float f) {
    return __uint_as_float(f2tf(f));
}

__device__ __forceinline__ void mma8(float* c, const unsigned* a, const unsigned* b) {
    asm volatile("mma.sync.aligned.m16n8k8.row.col.f32.tf32.tf32.f32 "
        "{%0,%1,%2,%3},{%4,%5,%6,%7},{%8,%9},{%0,%1,%2,%3};"
        : "+f"(c[0]), "+f"(c[1]), "+f"(c[2]), "+f"(c[3])
        : "r"(a[0]), "r"(a[1]), "r"(a[2]), "r"(a[3]), "r"(b[0]), "r"(b[1]));
}

__device__ __forceinline__ void ldsm4(unsigned& r0, unsigned& r1, unsigned& r2, unsigned& r3,
                                      const unsigned* p) {
    unsigned a = (unsigned)__cvta_generic_to_shared(p);
    asm volatile("ldmatrix.sync.aligned.m8n8.x4.shared.b16 {%0,%1,%2,%3},[%4];"
        : "=r"(r0), "=r"(r1), "=r"(r2), "=r"(r3) : "r"(a));
}

__device__ __forceinline__ void cpa16(unsigned* dst, const void* src) {
    unsigned d = (unsigned)__cvta_generic_to_shared(dst);
    asm volatile("cp.async.ca.shared.global [%0], [%1], 16;" :: "r"(d), "l"(src));
}
#define CP_COMMIT() asm volatile("cp.async.commit_group;")
#define CP_WAIT(N)  asm volatile("cp.async.wait_group %0;" :: "n"(N))

// 128B-row swizzles: full 8-group XOR -> conflict-free STS/LDGSTS.128 and LDSM
__device__ __forceinline__ int sw32(int m, int k) {   // rows of 32 floats
    return m*32 + (((((k) >> 2) ^ (m & 7)) << 2) | (k & 3));
}
__device__ __forceinline__ int sw64(int r, int c) {   // rows of 64 floats
    return r*64 + (((((c) >> 2) ^ (r & 7)) << 2) | (c & 3));
}

#define BK     32
#define TBUF   (128*BK)
#define STG    (2*TBUF)
#define NSTAGE 3
#define GEMM_SMEM_BYTES (NSTAGE * STG * (int)sizeof(unsigned))   // 96KB

// ============ kernel 0: tf32 pre-conversion ============
__global__ __launch_bounds__(256) void prep_kernel(const float* __restrict__ src,
                                                   float* __restrict__ dst, int n4)
{
    int i = blockIdx.x * blockDim.x + threadIdx.x;
    if (i < n4) {
        float4 v = ((const float4*)src)[i];
        v.x = f2tff(v.x); v.y = f2tff(v.y); v.z = f2tff(v.z); v.w = f2tff(v.w);
        ((float4*)dst)[i] = v;
    }
}

// ============ 128x128 NT GEMM core, cp.async 3-stage pipeline ============
__device__ __forceinline__ void gemm_core(
    const float* __restrict__ A, const float* __restrict__ W,
    int row0, int col0, unsigned* smem, float acc[2][8][4])
{
    const int K = EMBED;
    int tid  = threadIdx.x;
    int lane = tid & 31, wid = tid >> 5;
    int wm = wid >> 1, wn = wid & 1;

    #pragma unroll
    for (int mt = 0; mt < 2; mt++)
        #pragma unroll
        for (int nt = 0; nt < 8; nt++)
            #pragma unroll
            for (int i = 0; i < 4; i++) acc[mt][nt][i] = 0.f;

    int fr[4], fc[4];
    #pragma unroll
    for (int i = 0; i < 4; i++) { int f = tid + 256*i; fr[i] = f >> 3; fc[i] = (f & 7) * 4; }

    int offA[2][4], offB[4][4];
    {
        int eA = (lane & 16) ? 4 : 0;
        int eB = (lane & 8)  ? 4 : 0;
        #pragma unroll
        for (int mt = 0; mt < 2; mt++) {
            int r = wm*32 + mt*16 + (lane & 15);
            #pragma unroll
            for (int s = 0; s < 4; s++) offA[mt][s] = sw32(r, s*8 + eA);
        }
        #pragma unroll
        for (int p = 0; p < 4; p++) {
            int r = wn*64 + p*16 + (lane & 7) + ((lane >> 4) & 1) * 8;
            #pragma unroll
            for (int s = 0; s < 4; s++) offB[p][s] = sw32(r, s*8 + eB);
        }
    }

    const float* Abase = A + (size_t)row0 * K;
    const float* Bbase = W + (size_t)col0 * K;

    auto issue = [&](int kt) {
        unsigned* st = smem + (kt % NSTAGE) * STG;
        const float* Ab = Abase + kt * BK;
        const float* Bb = Bbase + kt * BK;
        #pragma unroll
        for (int i = 0; i < 4; i++)
            cpa16(st + sw32(fr[i], fc[i]), Ab + (size_t)fr[i] * K + fc[i]);
        #pragma unroll
        for (int i = 0; i < 4; i++)
            cpa16(st + TBUF + sw32(fr[i], fc[i]), Bb + (size_t)fr[i] * K + fc[i]);
        CP_COMMIT();
    };

    const int NK = K / BK;   // 32
    issue(0); issue(1);
    for (int kt = 0; kt < NK; kt++) {
        if (kt + 1 < NK) { CP_WAIT(1); } else { CP_WAIT(0); }
        __syncthreads();
        if (kt + 2 < NK) issue(kt + 2);
        const unsigned* Ab = smem + (kt % NSTAGE) * STG;
        const unsigned* Bb = Ab + TBUF;
        #pragma unroll
        for (int s = 0; s < 4; s++) {
            unsigned a[2][4], b[8][2];
            #pragma unroll
            for (int mt = 0; mt < 2; mt++)
                ldsm4(a[mt][0], a[mt][1], a[mt][2], a[mt][3], Ab + offA[mt][s]);
            #pragma unroll
            for (int p = 0; p < 4; p++)
                ldsm4(b[2*p][0], b[2*p][1], b[2*p+1][0], b[2*p+1][1], Bb + offB[p][s]);
            #pragma unroll
            for (int mt = 0; mt < 2; mt++)
                #pragma unroll
                for (int nt = 0; nt < 8; nt++)
                    mma8(acc[mt][nt], a[mt], b[nt]);
        }
    }
}

// ============ Kernel 1: fused QKV projections (grid.z picks Q/K/V) ============
// V is written TRANSPOSED into g_v[b,h,d,s].
__global__ __launch_bounds__(256, 2) void qkv_kernel()
{
    extern __shared__ __align__(16) unsigned smem[];
    int row0 = blockIdx.y * 128, col0 = blockIdx.x * 128;
    int z = blockIdx.z;
    const float* W = (z == 0) ? g_wq : (z == 1 ? g_wk : g_wv);
    float scale    = (z == 0) ? 0.125f : 1.0f;

    float acc[2][8][4];
    gemm_core(g_x, W, row0, col0, smem, acc);

    int lane = threadIdx.x & 31, wid = threadIdx.x >> 5;
    int g = lane >> 2, tg = lane & 3, wm = wid >> 1, wn = wid & 1;
    #pragma unroll
    for (int mt = 0; mt < 2; mt++) {
        int r = row0 + wm*32 + mt*16 + g;
        int bb = r >> 11, ss = r & 2047;
        #pragma unroll
        for (int nt = 0; nt < 8; nt++) {
            int c = col0 + wn*64 + nt*8 + 2*tg;
            int h = c >> 6, d = c & 63;
            if (z == 2) {
                // g_v[b,h,d,s]
                float* pv = g_v + (((size_t)(bb*NHEAD + h) * DK + d) * SEQ + ss);
                pv[0]       = f2tff(acc[mt][nt][0]);
                pv[SEQ]     = f2tff(acc[mt][nt][1]);
                pv[8]       = f2tff(acc[mt][nt][2]);
                pv[SEQ + 8] = f2tff(acc[mt][nt][3]);
            } else {
                float* dst = (z == 0) ? g_q : g_k;
                float* p0 = dst + (((size_t)(bb*NHEAD + h) * SEQ + ss) * DK + d);
                float* p1 = p0 + 8*DK;
                p0[0] = f2tff(acc[mt][nt][0] * scale); p0[1] = f2tff(acc[mt][nt][1] * scale);
                p1[0] = f2tff(acc[mt][nt][2] * scale); p1[1] = f2tff(acc[mt][nt][3] * scale);
            }
        }
    }
}

// ============ Kernel 2: flash attention ============
// 64q x 64k tiles, 128 threads = 4 warps (16 q-rows each). Q frags hoisted to
// registers; K and Vt both consumed via conflict-free ldmatrix; double-buffered.
#define ATTN_SMEM_BYTES (6 * 64 * 64 * (int)sizeof(unsigned))   // 96KB
__global__ __launch_bounds__(128, 2) void attn_kernel()
{
    extern __shared__ __align__(16) unsigned asm_[];
    unsigned* Qs = asm_;
    unsigned* Ps = asm_ + 4096;
    unsigned* KV = asm_ + 8192;   // stage s: K at s*8192, Vt at s*8192+4096

    int qt = blockIdx.x, bh = blockIdx.y;
    const float* Qp = g_q + (size_t)bh * SEQ * DK + (size_t)qt * 64 * DK;
    const float* Kp = g_k + (size_t)bh * SEQ * DK;
    const float* Vp = g_v + (size_t)bh * DK * SEQ;   // [d, s]

    int tid = threadIdx.x, lane = tid & 31, wid = tid >> 5;
    int g = lane >> 2, tg = lane & 3;
    int r0 = wid*16 + g;

    int eA = (lane & 16) ? 4 : 0;
    int rA = wid*16 + (lane & 15);
    int eB = (lane & 8)  ? 4 : 0;
    int rB[4];
    #pragma unroll
    for (int p = 0; p < 4; p++) rB[p] = p*16 + (lane & 7) + ((lane >> 4) & 1) * 8;

    int adS[8], goff[8], goffV[8];
    #pragma unroll
    for (int i = 0; i < 8; i++) {
        int f = tid + 128*i;
        int r = f >> 4, c4 = f & 15;
        adS[i]   = r*64 + ((c4 ^ (r & 7)) << 2);
        goff[i]  = r*64 + c4*4;       // K/Q: row=token, 64 contiguous
        goffV[i] = r*SEQ + c4*4;      // Vt:  row=d, SEQ-stride rows
    }

    // Q fill, then first K/Vt fill
    #pragma unroll
    for (int i = 0; i < 8; i++) cpa16(Qs + adS[i], Qp + goff[i]);
    CP_COMMIT();
    #pragma unroll
    for (int i = 0; i < 8; i++) {
        cpa16(KV + adS[i],        Kp + goff[i]);
        cpa16(KV + 4096 + adS[i], Vp + goffV[i]);
    }
    CP_COMMIT();

    // hoist Q fragments (reused for all 32 key tiles)
    unsigned aq[8][4];
    CP_WAIT(1);
    __syncthreads();
    #pragma unroll
    for (int kk8 = 0; kk8 < 8; kk8++)
        ldsm4(aq[kk8][0], aq[kk8][1], aq[kk8][2], aq[kk8][3], Qs + sw64(rA, kk8*8 + eA));

    float o[8][4];
    #pragma unroll
    for (int nt = 0; nt < 8; nt++)
        #pragma unroll
        for (int i = 0; i < 4; i++) o[nt][i] = 0.f;
    float m0 = -1e30f, m1 = -1e30f, l0 = 0.f, l1 = 0.f;

    const int NT = SEQ/64;
    for (int kt = 0; kt < NT; kt++) {
        CP_WAIT(0);
        __syncthreads();

        if (kt + 1 < NT) {
            unsigned* st = KV + ((kt + 1) & 1) * 8192;
            int t  = (kt + 1) * 64;
            #pragma unroll
            for (int i = 0; i < 8; i++) {
                cpa16(st + adS[i],        Kp + (size_t)t * DK + goff[i]);
                cpa16(st + 4096 + adS[i], Vp + t + goffV[i]);
            }
            CP_COMMIT();
        }

        const unsigned* Ks  = KV + (kt & 1) * 8192;
        const unsigned* Vts = Ks + 4096;

        // S = Q * K^T
        float s[8][4];
        #pragma unroll
        for (int nt = 0; nt < 8; nt++)
            #pragma unroll
            for (int i = 0; i < 4; i++) s[nt][i] = 0.f;
        #pragma unroll
        for (int kk8 = 0; kk8 < 8; kk8++) {
            unsigned b[8][2];
            #pragma unroll
            for (int p = 0; p < 4; p++)
                ldsm4(b[2*p][0], b[2*p][1], b[2*p+1][0], b[2*p+1][1],
                      Ks + sw64(rB[p], kk8*8 + eB));
            #pragma unroll
            for (int nt = 0; nt < 8; nt++) mma8(s[nt], aq[kk8], b[nt]);
        }

        // online softmax
        float ml0 = -1e30f, ml1 = -1e30f;
        #pragma unroll
        for (int nt = 0; nt < 8; nt++) {
            ml0 = fmaxf(ml0, fmaxf(s[nt][0], s[nt][1]));
            ml1 = fmaxf(ml1, fmaxf(s[nt][2], s[nt][3]));
        }
        ml0 = fmaxf(ml0, __shfl_xor_sync(0xffffffffu, ml0, 1));
        ml0 = fmaxf(ml0, __shfl_xor_sync(0xffffffffu, ml0, 2));
        ml1 = fmaxf(ml1, __shfl_xor_sync(0xffffffffu, ml1, 1));
        ml1 = fmaxf(ml1, __shfl_xor_sync(0xffffffffu, ml1, 2));
        float mn0 = fmaxf(m0, ml0), mn1 = fmaxf(m1, ml1);
        float al0 = __expf(m0 - mn0), al1 = __expf(m1 - mn1);
        m0 = mn0; m1 = mn1;
        float sum0 = 0.f, sum1 = 0.f;
        #pragma unroll
        for (int nt = 0; nt < 8; nt++) {
            s[nt][0] = __expf(s[nt][0] - mn0); sum0 += s[nt][0];
            s[nt][1] = __expf(s[nt][1] - mn0); sum0 += s[nt][1];
            s[nt][2] = __expf(s[nt][2] - mn1); sum1 += s[nt][2];
            s[nt][3] = __expf(s[nt][3] - mn1); sum1 += s[nt][3];
        }
        sum0 += __shfl_xor_sync(0xffffffffu, sum0, 1);
        sum0 += __shfl_xor_sync(0xffffffffu, sum0, 2);
        sum1 += __shfl_xor_sync(0xffffffffu, sum1, 1);
        sum1 += __shfl_xor_sync(0xffffffffu, sum1, 2);
        l0 = l0 * al0 + sum0;
        l1 = l1 * al1 + sum1;
        #pragma unroll
        for (int nt = 0; nt < 8; nt++) {
            o[nt][0] *= al0; o[nt][1] *= al0;
            o[nt][2] *= al1; o[nt][3] *= al1;
        }

        // P stripe -> Ps (warp-private rows)
        #pragma unroll
        for (int nt = 0; nt < 8; nt++) {
            int c = nt*8 + 2*tg;
            Ps[sw64(r0,     c)]     = f2tf(s[nt][0]);
            Ps[sw64(r0,     c + 1)] = f2tf(s[nt][1]);
            Ps[sw64(r0 + 8, c)]     = f2tf(s[nt][2]);
            Ps[sw64(r0 + 8, c + 1)] = f2tf(s[nt][3]);
        }
        __syncwarp();

        // O += P * V   (B fragment from Vt via ldmatrix, same sites as K)
        #pragma unroll
        for (int kk8 = 0; kk8 < 8; kk8++) {
            unsigned a[4], b[8][2];
            ldsm4(a[0], a[1], a[2], a[3], Ps + sw64(rA, kk8*8 + eA));
            #pragma unroll
            for (int p = 0; p < 4; p++)
                ldsm4(b[2*p][0], b[2*p][1], b[2*p+1][0], b[2*p+1][1],
                      Vts + sw64(rB[p], kk8*8 + eB));
            #pragma unroll
            for (int nt = 0; nt < 8; nt++) mma8(o[nt], a, b[nt]);
        }
    }

    // epilogue
    float inv0 = 1.f / l0, inv1 = 1.f / l1;
    int bb = bh >> 4, h = bh & 15;
    int q0 = qt*64 + r0;
    float* base0 = g_attn + ((size_t)(bb*SEQ + q0) * EMBED) + h*64;
    float* base1 = base0 + (size_t)8 * EMBED;
    #pragma unroll
    for (int nt = 0; nt < 8; nt++) {
        int d = nt*8 + 2*tg;
        base0[d]     = f2tff(o[nt][0] * inv0);
        base0[d + 1] = f2tff(o[nt][1] * inv0);
        base1[d]     = f2tff(o[nt][2] * inv1);
        base1[d + 1] = f2tff(o[nt][3] * inv1);
    }
}

// ============ Kernel 3: output projection ============
__global__ __launch_bounds__(256, 2) void oproj_kernel(float* __restrict__ out)
{
    extern __shared__ __align__(16) unsigned smem[];
    int row0 = blockIdx.y * 128, col0 = blockIdx.x * 128;
    float acc[2][8][4];
    gemm_core(g_attn, g_wo, row0, col0, smem, acc);

    int lane = threadIdx.x & 31, wid = threadIdx.x >> 5;
    int g = lane >> 2, tg = lane & 3, wm = wid >> 1, wn = wid & 1;
    #pragma unroll
    for (int mt = 0; mt < 2; mt++) {
        int r = row0 + wm*32 + mt*16 + g;
        #pragma unroll
        for (int nt = 0; nt < 8; nt++) {
            int c = col0 + wn*64 + nt*8 + 2*tg;
            float* p0 = out + (size_t)r * EMBED + c;
            float* p1 = out + (size_t)(r + 8) * EMBED + c;
            p0[0] = acc[mt][nt][0]; p0[1] = acc[mt][nt][1];
            p1[0] = acc[mt][nt][2]; p1[1] = acc[mt][nt][3];
        }
    }
}

// ============ launch ============
extern "C" void kernel_launch(void* const* d_in, const int* in_sizes, int n_in,
                              void* d_out, int out_size)
{
    const float* x  = (const float*)d_in[0];
    const float* Wq = (const float*)d_in[1];
    const float* Wk = (const float*)d_in[2];
    const float* Wv = (const float*)d_in[3];
    const float* Wo = (const float*)d_in[4];
    float* out = (float*)d_out;

    cudaFuncSetAttribute(qkv_kernel,   cudaFuncAttributeMaxDynamicSharedMemorySize, GEMM_SMEM_BYTES);
    cudaFuncSetAttribute(oproj_kernel, cudaFuncAttributeMaxDynamicSharedMemorySize, GEMM_SMEM_BYTES);
    cudaFuncSetAttribute(attn_kernel,  cudaFuncAttributeMaxDynamicSharedMemorySize, ATTN_SMEM_BYTES);

    float* p_x;  cudaGetSymbolAddress((void**)&p_x,  g_x);
    float* p_wq; cudaGetSymbolAddress((void**)&p_wq, g_wq);
    float* p_wk; cudaGetSymbolAddress((void**)&p_wk, g_wk);
    float* p_wv; cudaGetSymbolAddress((void**)&p_wv, g_wv);
    float* p_wo; cudaGetSymbolAddress((void**)&p_wo, g_wo);

    int nx4 = MTOK*EMBED/4, nw4 = EMBED*EMBED/4;
    prep_kernel<<<(nx4 + 255)/256, 256>>>(x,  p_x,  nx4);
    prep_kernel<<<(nw4 + 255)/256, 256>>>(Wq, p_wq, nw4);
    prep_kernel<<<(nw4 + 255)/256, 256>>>(Wk, p_wk, nw4);
    prep_kernel<<<(nw4 + 255)/256, 256>>>(Wv, p_wv, nw4);
    prep_kernel<<<(nw4 + 255)/256, 256>>>(Wo, p_wo, nw4);

    qkv_kernel<<<dim3(EMBED/128, MTOK/128, 3), 256, GEMM_SMEM_BYTES>>>();
    attn_kernel<<<dim3(SEQ/64, BATCH*NHEAD), 128, ATTN_SMEM_BYTES>>>();
    oproj_kernel<<<dim3(EMBED/128, MTOK/128), 256, GEMM_SMEM_BYTES>>>(out);
}